// round 15
// baseline (speedup 1.0000x reference)
#include <cuda_runtime.h>
#include <cstdint>

#define N_ELEM   524288      // 8*256*256
#define N_H      (N_ELEM / 2)
#define PLANES   112         // 4*28
#define HALF_P   56          // planes per half
#define QTR_P    28          // mid-stream insert point
#define PLANE_F4 16384       // 65536/4
#define ROWS_F4  1835008     // PLANES*PLANE_F4
#define CHAIN    48
#define NBLK     1024
#define NTHR     256         // warps 0-3: planes 0..55 ; warps 4-7: planes 56..111
#define PAIRS    128
#define STAGES   3
#define CHUNK_B  2048u       // per-tensor per-plane block chunk

// persistent-kernel globals (replay-safe)
__device__ unsigned g_barrier = 0;
__device__ int      g_F       = 0;

// ================= compile-time threefry: key chains are constants ============
struct CU2 { uint32_t x, y; };

constexpr uint32_t crotl(uint32_t v, int r) { return (v << r) | (v >> (32 - r)); }

constexpr CU2 ctf(uint32_t k0, uint32_t k1, uint32_t x0, uint32_t x1)
{
    uint32_t k2 = k0 ^ k1 ^ 0x1BD11BDAu;
    x0 += k0; x1 += k1;
    x0 += x1; x1 = crotl(x1,13); x1 ^= x0;
    x0 += x1; x1 = crotl(x1,15); x1 ^= x0;
    x0 += x1; x1 = crotl(x1,26); x1 ^= x0;
    x0 += x1; x1 = crotl(x1, 6); x1 ^= x0;
    x0 += k1; x1 += k2 + 1u;
    x0 += x1; x1 = crotl(x1,17); x1 ^= x0;
    x0 += x1; x1 = crotl(x1,29); x1 ^= x0;
    x0 += x1; x1 = crotl(x1,16); x1 ^= x0;
    x0 += x1; x1 = crotl(x1,24); x1 ^= x0;
    x0 += k2; x1 += k0 + 2u;
    x0 += x1; x1 = crotl(x1,13); x1 ^= x0;
    x0 += x1; x1 = crotl(x1,15); x1 ^= x0;
    x0 += x1; x1 = crotl(x1,26); x1 ^= x0;
    x0 += x1; x1 = crotl(x1, 6); x1 ^= x0;
    x0 += k0; x1 += k1 + 3u;
    x0 += x1; x1 = crotl(x1,17); x1 ^= x0;
    x0 += x1; x1 = crotl(x1,29); x1 ^= x0;
    x0 += x1; x1 = crotl(x1,16); x1 ^= x0;
    x0 += x1; x1 = crotl(x1,24); x1 ^= x0;
    x0 += k1; x1 += k2 + 4u;
    x0 += x1; x1 = crotl(x1,13); x1 ^= x0;
    x0 += x1; x1 = crotl(x1,15); x1 ^= x0;
    x0 += x1; x1 = crotl(x1,26); x1 ^= x0;
    x0 += x1; x1 = crotl(x1, 6); x1 ^= x0;
    x0 += k2; x1 += k0 + 5u;
    return CU2{x0, x1};
}

struct alignas(16) Tabs {
    uint32_t rej[CHAIN][4];
    uint32_t kn [CHAIN][2];
    uint32_t knp[CHAIN][2];
    uint32_t kg [2];
};

constexpr Tabs make_tabs()
{
    Tabs T{};
    CU2 kp = ctf(0u, 1u, 0u, 0u);
    CU2 kd = ctf(0u, 1u, 0u, 1u);
    CU2 kg = ctf(0u, 1u, 0u, 2u);
    T.kg[0] = kg.x; T.kg[1] = kg.y;
    CU2 key = kp;
    for (int t = 0; t < CHAIN; ++t) {
        CU2 nk = ctf(key.x, key.y, 0u, 0u);
        CU2 s0 = ctf(key.x, key.y, 0u, 1u);
        CU2 s1 = ctf(key.x, key.y, 0u, 2u);
        T.rej[t][0] = s0.x; T.rej[t][1] = s0.y;
        T.rej[t][2] = s1.x; T.rej[t][3] = s1.y;
        key = nk;
    }
    key = kd;
    for (int t = 0; t < CHAIN; ++t) {
        CU2 nk  = ctf(key.x, key.y, 0u, 0u);
        CU2 sub = ctf(key.x, key.y, 0u, 1u);
        T.kn[t][0] = sub.x; T.kn[t][1] = sub.y;
        key = nk;
    }
    key = kp;
    for (int t = 0; t < CHAIN; ++t) {
        CU2 nk  = ctf(key.x, key.y, 0u, 0u);
        CU2 sub = ctf(key.x, key.y, 0u, 1u);
        T.knp[t][0] = sub.x; T.knp[t][1] = sub.y;
        key = nk;
    }
    return T;
}

__constant__ Tabs c_tabs = make_tabs();

// ---------------- Threefry-2x32 device --------------------------------------
__device__ __forceinline__ uint2 tf2x32(uint32_t k0, uint32_t k1,
                                        uint32_t x0, uint32_t x1)
{
    uint32_t k2 = k0 ^ k1 ^ 0x1BD11BDAu;
    x0 += k0; x1 += k1;
#define TF_RND(r) { x0 += x1; x1 = __funnelshift_l(x1, x1, (r)); x1 ^= x0; }
    TF_RND(13) TF_RND(15) TF_RND(26) TF_RND(6)
    x0 += k1; x1 += k2 + 1u;
    TF_RND(17) TF_RND(29) TF_RND(16) TF_RND(24)
    x0 += k2; x1 += k0 + 2u;
    TF_RND(13) TF_RND(15) TF_RND(26) TF_RND(6)
    x0 += k0; x1 += k1 + 3u;
    TF_RND(17) TF_RND(29) TF_RND(16) TF_RND(24)
    x0 += k1; x1 += k2 + 4u;
    TF_RND(13) TF_RND(15) TF_RND(26) TF_RND(6)
    x0 += k2; x1 += k0 + 5u;
#undef TF_RND
    return make_uint2(x0, x1);
}

__device__ __forceinline__ uint32_t rbits(uint2 k, uint32_t i)
{
    uint2 r = tf2x32(k.x, k.y, 0u, i);
    return r.x ^ r.y;
}

__device__ __forceinline__ float u01(uint32_t bits)
{
    return __uint_as_float((bits >> 9) | 0x3f800000u) - 1.0f;
}

// ---------------- XLA-style lgamma (Lanczos g=7, f32) ------------------------
__device__ __forceinline__ float lgamma_xla(float x)
{
    float z = __fsub_rn(x, 1.0f);
    float sum = 0.99999999999980993f;
    sum = __fadd_rn(sum, __fdiv_rn(676.5203681218851f,      __fadd_rn(z, 1.0f)));
    sum = __fadd_rn(sum, __fdiv_rn(-1259.1392167224028f,    __fadd_rn(z, 2.0f)));
    sum = __fadd_rn(sum, __fdiv_rn(771.32342877765313f,     __fadd_rn(z, 3.0f)));
    sum = __fadd_rn(sum, __fdiv_rn(-176.61502916214059f,    __fadd_rn(z, 4.0f)));
    sum = __fadd_rn(sum, __fdiv_rn(12.507343278686905f,     __fadd_rn(z, 5.0f)));
    sum = __fadd_rn(sum, __fdiv_rn(-0.13857109526572012f,   __fadd_rn(z, 6.0f)));
    sum = __fadd_rn(sum, __fdiv_rn(9.9843695780195716e-6f,  __fadd_rn(z, 7.0f)));
    sum = __fadd_rn(sum, __fdiv_rn(1.5056327351493116e-7f,  __fadd_rn(z, 8.0f)));
    float t     = __fadd_rn(7.5f, z);
    float log_t = __fadd_rn(2.0149030205422647f, log1pf(__fdiv_rn(z, 7.5f)));
    float r = __fadd_rn(0.91893853320467274f, __fmul_rn(__fadd_rn(z, 0.5f), log_t));
    r = __fsub_rn(r, t);
    r = __fadd_rn(r, logf(sum));
    return r;
}

// ---------------- XLA erf_inv (Giles polynomial, f32) ------------------------
__device__ __forceinline__ float erfinv_xla(float x)
{
    float w = -log1pf(-__fmul_rn(x, x));
    float p;
    if (w < 5.0f) {
        w = __fsub_rn(w, 2.5f);
        p = 2.81022636e-08f;
        p = fmaf(p, w, 3.43273939e-07f);
        p = fmaf(p, w, -3.5233877e-06f);
        p = fmaf(p, w, -4.39150654e-06f);
        p = fmaf(p, w, 0.00021858087f);
        p = fmaf(p, w, -0.00125372503f);
        p = fmaf(p, w, -0.00417768164f);
        p = fmaf(p, w, 0.246640727f);
        p = fmaf(p, w, 1.50140941f);
    } else {
        w = __fsub_rn(sqrtf(w), 3.0f);
        p = -0.000200214257f;
        p = fmaf(p, w, 0.000100950558f);
        p = fmaf(p, w, 0.00134934322f);
        p = fmaf(p, w, -0.00367342844f);
        p = fmaf(p, w, 0.00573950773f);
        p = fmaf(p, w, -0.0076224613f);
        p = fmaf(p, w, 0.00943887047f);
        p = fmaf(p, w, 1.00167406f);
        p = fmaf(p, w, 2.83297682f);
    }
    return __fmul_rn(p, x);
}

// ---------------- Poisson: Knuth (lam < 10) ----------------------------------
__device__ __forceinline__ float poisson_knuth(float lam, uint32_t i,
                                               const uint32_t (*ch)[2])
{
    float neg = -lam;
    float lp = 0.0f;
    float k  = 0.0f;
#pragma unroll 1
    for (int t = 0; t < CHAIN; ++t) {
        if (!(lp > neg)) break;
        k  = __fadd_rn(k, 1.0f);
        lp = __fadd_rn(lp, logf(u01(rbits(make_uint2(ch[t][0], ch[t][1]), i))));
    }
    return __fsub_rn(k, 1.0f);
}

// ---------------- Hormann rejection ------------------------------------------
struct RejP { float lam, log_lam, b, a, inv_alpha, v_r, two_a; };

__device__ __forceinline__ RejP make_rejp(float lam)
{
    RejP P;
    P.lam       = lam;
    P.log_lam   = logf(lam);
    P.b         = __fadd_rn(0.931f, __fmul_rn(2.53f, sqrtf(lam)));
    P.a         = __fadd_rn(-0.059f, __fmul_rn(0.02483f, P.b));
    P.inv_alpha = __fadd_rn(1.1239f, __fdiv_rn(1.1328f, __fsub_rn(P.b, 3.4f)));
    P.v_r       = __fsub_rn(0.9277f, __fdiv_rn(3.6224f, __fsub_rn(P.b, 2.0f)));
    P.two_a     = __fmul_rn(2.0f, P.a);
    return P;
}

__device__ __forceinline__ bool rej_step(const RejP& P, uint32_t i, uint4 c,
                                         float* kout)
{
    float u  = __fsub_rn(u01(rbits(make_uint2(c.x, c.y), i)), 0.5f);
    float v  = u01(rbits(make_uint2(c.z, c.w), i));
    float us = __fsub_rn(0.5f, fabsf(u));
    float k  = floorf(__fadd_rn(__fadd_rn(
                 __fmul_rn(__fadd_rn(__fdiv_rn(P.two_a, us), P.b), u), P.lam), 0.43f));
    *kout = k;

    if ((us >= 0.07f) && (v <= P.v_r)) return true;                 // accept1
    if ((k < 0.0f) || ((us < 0.013f) && (v > us))) return false;    // reject

    float s = logf(__fdiv_rn(__fmul_rn(v, P.inv_alpha),
                   __fadd_rn(__fdiv_rn(P.a, __fmul_rn(us, us)), P.b)));
    float t = __fsub_rn(__fadd_rn(-P.lam, __fmul_rn(k, P.log_lam)),
                        lgamma_xla(__fadd_rn(k, 1.0f)));
    return (s <= t);                                                 // accept2
}

__device__ __forceinline__ uint4 rej_key(int t)
{
    return *reinterpret_cast<const uint4*>(c_tabs.rej[t]);
}

// ---------------- mbarrier + bulk-copy PTX helpers ----------------------------
__device__ __forceinline__ uint32_t smem_u32(const void* p)
{
    return (uint32_t)__cvta_generic_to_shared(p);
}
__device__ __forceinline__ void mbar_init(uint32_t a, uint32_t cnt)
{
    asm volatile("mbarrier.init.shared.b64 [%0], %1;" :: "r"(a), "r"(cnt) : "memory");
}
__device__ __forceinline__ void mbar_expect_tx(uint32_t a, uint32_t bytes)
{
    asm volatile("mbarrier.arrive.expect_tx.shared.b64 _, [%0], %1;"
                 :: "r"(a), "r"(bytes) : "memory");
}
__device__ __forceinline__ void mbar_arrive(uint32_t a)
{
    asm volatile("mbarrier.arrive.shared.b64 _, [%0];" :: "r"(a) : "memory");
}
__device__ __forceinline__ void bulk_g2s(uint32_t dst, const void* src, uint32_t mbar)
{
    asm volatile(
        "cp.async.bulk.shared::cluster.global.mbarrier::complete_tx::bytes "
        "[%0], [%1], %2, [%3];"
        :: "r"(dst), "l"(src), "r"(CHUNK_B), "r"(mbar) : "memory");
}
__device__ __forceinline__ void mbar_wait(uint32_t a, uint32_t parity)
{
    uint32_t done;
    asm volatile("{\n\t.reg .pred p;\n\t"
        "mbarrier.try_wait.parity.acquire.cta.shared::cta.b64 p, [%1], %2;\n\t"
        "selp.b32 %0, 1, 0, p;\n\t}"
        : "=r"(done) : "r"(a), "r"(parity) : "memory");
    while (!done) {
        asm volatile("{\n\t.reg .pred p;\n\t"
            "mbarrier.try_wait.parity.acquire.cta.shared::cta.b64 p, [%1], %2, 0x989680;\n\t"
            "selp.b32 %0, 1, 0, p;\n\t}"
            : "=r"(done) : "r"(a), "r"(parity) : "memory");
    }
}

// ================================================================================
// Fused persistent kernel, bulk-copy (UBLKCP) streaming pipeline:
// 1024 blocks x 256 threads, pair-split planes (warps 0-3: planes 0..55,
// warps 4-7: 56..111). Per half: 3-stage smem pipeline, producer = thread pl==0
// issues 2x2KB cp.async.bulk per plane; 128 consumers LDS+FMA in ascending plane
// order (lam bit-identical to R12/R13). Grid barrier + backward scan unchanged.
// __launch_bounds__(256, 7): 148*7=1036 >= 1024 co-resident => barrier safe.
// ================================================================================
__global__ void __launch_bounds__(NTHR, 7)
capF(const float* __restrict__ spec, const float* __restrict__ filt,
     float* __restrict__ out)
{
    __shared__ alignas(128) float4 buf[2][STAGES][2][PAIRS]; // 24KB
    __shared__ uint64_t mb_full[2][STAGES];
    __shared__ uint64_t mb_empty[2][STAGES];
    __shared__ float4 sh[2][PAIRS];    // per-half partial sums (4KB)
    __shared__ int s_fmax;
    __shared__ int s_F;

    const int tid = threadIdx.x;
    if (tid == 0) {
        s_fmax = 0;
#pragma unroll
        for (int h = 0; h < 2; ++h)
#pragma unroll
            for (int st = 0; st < STAGES; ++st) {
                mbar_init(smem_u32(&mb_full[h][st]), 1u);
                mbar_init(smem_u32(&mb_empty[h][st]), (uint32_t)PAIRS);
            }
    }
    __syncthreads();

    const int s  = tid >> 7;                       // half: 0 or 1
    const int pl = tid & 127;
    const int pair_gid = blockIdx.x * PAIRS + pl;
    const int e0  = pair_gid << 2;
    const int b   = e0 >> 16;
    const int p0  = s * HALF_P;

    // block chunk base (2KB-aligned): 512 elements per block within one plane
    const int hw4b = (blockIdx.x * PAIRS) & 16383;
    const float4* sp_blk = reinterpret_cast<const float4*>(spec)
                           + (long)b * ROWS_F4 + (long)p0 * PLANE_F4 + hw4b;
    const float4* fp_blk = reinterpret_cast<const float4*>(filt)
                           + (long)b * ROWS_F4 + (long)p0 * PLANE_F4 + hw4b;

    // prime pipeline: producer fills all 3 stages
    if (pl == 0) {
#pragma unroll
        for (int st = 0; st < STAGES; ++st) {
            const uint32_t fb = smem_u32(&mb_full[s][st]);
            mbar_expect_tx(fb, 2 * CHUNK_B);
            bulk_g2s(smem_u32(&buf[s][st][0][0]), sp_blk + (long)st * PLANE_F4, fb);
            bulk_g2s(smem_u32(&buf[s][st][1][0]), fp_blk + (long)st * PLANE_F4, fb);
        }
    }

    // constant output planes early
    float2* o2 = reinterpret_cast<float2*>(out);
    const int q2 = (e0 >> 1) + s;
    o2[2 * N_H + q2] = make_float2(0.5f, 0.5f);
    o2[3 * N_H + q2] = make_float2(0.25f, 0.25f);

    float4 acc = make_float4(0.f, 0.f, 0.f, 0.f);

#define CONSUME_PLANE(p)                                                        \
    {                                                                           \
        const int st  = (p) % STAGES;                                           \
        const uint32_t par = ((p) / STAGES) & 1;                                \
        mbar_wait(smem_u32(&mb_full[s][st]), par);                              \
        float4 a = buf[s][st][0][pl];                                           \
        float4 f = buf[s][st][1][pl];                                           \
        acc.x = __fadd_rn(acc.x, __fmul_rn(a.x, f.x));                          \
        acc.y = __fadd_rn(acc.y, __fmul_rn(a.y, f.y));                          \
        acc.z = __fadd_rn(acc.z, __fmul_rn(a.z, f.z));                          \
        acc.w = __fadd_rn(acc.w, __fmul_rn(a.w, f.w));                          \
        mbar_arrive(smem_u32(&mb_empty[s][st]));                                \
        if (pl == 0 && (p) + STAGES < HALF_P) {                                 \
            mbar_wait(smem_u32(&mb_empty[s][st]), par);                         \
            const uint32_t fb = smem_u32(&mb_full[s][st]);                      \
            mbar_expect_tx(fb, 2 * CHUNK_B);                                    \
            bulk_g2s(smem_u32(&buf[s][st][0][0]),                               \
                     sp_blk + (long)((p) + STAGES) * PLANE_F4, fb);             \
            bulk_g2s(smem_u32(&buf[s][st][1][0]),                               \
                     fp_blk + (long)((p) + STAGES) * PLANE_F4, fb);             \
        }                                                                       \
    }

    // ---- streaming quarter 1: my planes [0..28) ----
#pragma unroll 1
    for (int p = 0; p < QTR_P; ++p) CONSUME_PLANE(p)

    // ---- index-only RNG (dn, gn) for MY 2 elements ----
    const uint2 kg = make_uint2(c_tabs.kg[0], c_tabs.kg[1]);
    float raw2[2];
#pragma unroll 1
    for (int v = 0; v < 2; ++v) {
        const uint32_t i = (uint32_t)(e0 + 2 * s + v);
        float dn = poisson_knuth(0.5f, i, c_tabs.kn);

        float f  = u01(rbits(kg, i));
        float uu = __fadd_rn(__fmul_rn(f, 1.99999994f), -0.99999994f);
        uu = fmaxf(uu, -0.99999994f);
        float gn = __fmul_rn(__fmul_rn(1.4142135623730951f, erfinv_xla(uu)), 0.5f);

        raw2[v] = __fadd_rn(dn, gn);
    }

    // ---- streaming quarter 2: my planes [28..56) ----
#pragma unroll 1
    for (int p = QTR_P; p < HALF_P; ++p) CONSUME_PLANE(p)
#undef CONSUME_PLANE

    // ---- combine halves: lam = (h0 + h1) + CONS ----
    sh[s][pl] = acc;
    __syncthreads();
    const float4 h0 = sh[0][pl];
    const float4 h1 = sh[1][pl];

    float lam2[2];
    {
        const float h0v[4] = {h0.x, h0.y, h0.z, h0.w};
        const float h1v[4] = {h1.x, h1.y, h1.z, h1.w};
        lam2[0] = __fadd_rn(__fadd_rn(h0v[2 * s],     h1v[2 * s]),     1e-10f);
        lam2[1] = __fadd_rn(__fadd_rn(h0v[2 * s + 1], h1v[2 * s + 1]), 1e-10f);
    }

    o2[N_H + q2] = make_float2(lam2[0], lam2[1]);

    // ---- forward first-accept scan for my 2 elements ----
    int fmax = 0;
#pragma unroll 1
    for (int v = 0; v < 2; ++v) {
        const uint32_t i = (uint32_t)(e0 + 2 * s + v);
        const float lam_rej = (lam2[v] < 10.0f) ? 1e5f : lam2[v];
        RejP P = make_rejp(lam_rej);
        float kdum;
        int fe = CHAIN - 1;
#pragma unroll 1
        for (int t = 0; t < CHAIN; ++t) {
            if (rej_step(P, i, rej_key(t), &kdum)) { fe = t; break; }
        }
        fmax = max(fmax, fe);
    }
    atomicMax(&s_fmax, fmax);

    __syncthreads();                       // s_fmax final

    // ---- software grid barrier (replay-safe) ----
    if (tid == 0) {
        atomicMax(&g_F, s_fmax);
        __threadfence();
        unsigned ticket = atomicAdd(&g_barrier, 1u);
        if (ticket == NBLK - 1u) {
            atomicExch(&g_barrier, 0u);
        } else {
            while (*((volatile unsigned*)&g_barrier) != 0u)
                __nanosleep(64);
        }
        __threadfence();
        s_F = *((volatile int*)&g_F);
    }
    __syncthreads();
    const int F = min(s_F, CHAIN - 1);

    // ---- final: LAST accept via backward scan from F, my 2 elements ----
    float noisy2[2];
#pragma unroll 1
    for (int v = 0; v < 2; ++v) {
        const uint32_t i = (uint32_t)(e0 + 2 * s + v);
        const float lam = lam2[v];
        float pn;
        if (lam < 10.0f) {
            pn = poisson_knuth(lam, i, c_tabs.knp);
        } else {
            RejP P = make_rejp(lam);
            float pnk = -1.0f, k;
#pragma unroll 1
            for (int t = F; t >= 0; --t) {
                if (rej_step(P, i, rej_key(t), &k)) { pnk = k; break; }
            }
            pn = pnk;
        }
        noisy2[v] = __fdiv_rn(__fmul_rn(__fadd_rn(pn, raw2[v]), 10.0f), 255.0f);
    }

    o2[q2] = make_float2(noisy2[0], noisy2[1]);
}

extern "C" void kernel_launch(void* const* d_in, const int* in_sizes, int n_in,
                              void* d_out, int out_size)
{
    const float* spec = (const float*)d_in[0];
    const float* filt = (const float*)d_in[1];
    float* out = (float*)d_out;
    capF<<<NBLK, NTHR>>>(spec, filt, out);
}

// round 16
// speedup vs baseline: 1.1847x; 1.1847x over previous
#include <cuda_runtime.h>
#include <cstdint>

#define N_ELEM   524288      // 8*256*256
#define N_H      (N_ELEM / 2)
#define PLANES   112         // 4*28
#define HALF_P   56          // planes per pair-thread
#define QTR_P    28          // mid-stream insert point
#define PLANE_F4 16384       // 65536/4
#define ROWS_F4  1835008     // PLANES*PLANE_F4
#define CHAIN    48
#define NBLK     1024
#define NTHR     256         // warps 0-3: planes 0..55 ; warps 4-7: planes 56..111
#define PAIRS    128         // element groups per block
#define LGTAB    512

// persistent-kernel globals (replay-safe)
__device__ unsigned g_barrier = 0;
__device__ int      g_F       = 0;

// ================= compile-time threefry: key chains are constants ============
struct CU2 { uint32_t x, y; };

constexpr uint32_t crotl(uint32_t v, int r) { return (v << r) | (v >> (32 - r)); }

constexpr CU2 ctf(uint32_t k0, uint32_t k1, uint32_t x0, uint32_t x1)
{
    uint32_t k2 = k0 ^ k1 ^ 0x1BD11BDAu;
    x0 += k0; x1 += k1;
    x0 += x1; x1 = crotl(x1,13); x1 ^= x0;
    x0 += x1; x1 = crotl(x1,15); x1 ^= x0;
    x0 += x1; x1 = crotl(x1,26); x1 ^= x0;
    x0 += x1; x1 = crotl(x1, 6); x1 ^= x0;
    x0 += k1; x1 += k2 + 1u;
    x0 += x1; x1 = crotl(x1,17); x1 ^= x0;
    x0 += x1; x1 = crotl(x1,29); x1 ^= x0;
    x0 += x1; x1 = crotl(x1,16); x1 ^= x0;
    x0 += x1; x1 = crotl(x1,24); x1 ^= x0;
    x0 += k2; x1 += k0 + 2u;
    x0 += x1; x1 = crotl(x1,13); x1 ^= x0;
    x0 += x1; x1 = crotl(x1,15); x1 ^= x0;
    x0 += x1; x1 = crotl(x1,26); x1 ^= x0;
    x0 += x1; x1 = crotl(x1, 6); x1 ^= x0;
    x0 += k0; x1 += k1 + 3u;
    x0 += x1; x1 = crotl(x1,17); x1 ^= x0;
    x0 += x1; x1 = crotl(x1,29); x1 ^= x0;
    x0 += x1; x1 = crotl(x1,16); x1 ^= x0;
    x0 += x1; x1 = crotl(x1,24); x1 ^= x0;
    x0 += k1; x1 += k2 + 4u;
    x0 += x1; x1 = crotl(x1,13); x1 ^= x0;
    x0 += x1; x1 = crotl(x1,15); x1 ^= x0;
    x0 += x1; x1 = crotl(x1,26); x1 ^= x0;
    x0 += x1; x1 = crotl(x1, 6); x1 ^= x0;
    x0 += k2; x1 += k0 + 5u;
    return CU2{x0, x1};
}

struct alignas(16) Tabs {
    uint32_t rej[CHAIN][4];
    uint32_t kn [CHAIN][2];
    uint32_t knp[CHAIN][2];
    uint32_t kg [2];
};

constexpr Tabs make_tabs()
{
    Tabs T{};
    CU2 kp = ctf(0u, 1u, 0u, 0u);
    CU2 kd = ctf(0u, 1u, 0u, 1u);
    CU2 kg = ctf(0u, 1u, 0u, 2u);
    T.kg[0] = kg.x; T.kg[1] = kg.y;
    CU2 key = kp;
    for (int t = 0; t < CHAIN; ++t) {
        CU2 nk = ctf(key.x, key.y, 0u, 0u);
        CU2 s0 = ctf(key.x, key.y, 0u, 1u);
        CU2 s1 = ctf(key.x, key.y, 0u, 2u);
        T.rej[t][0] = s0.x; T.rej[t][1] = s0.y;
        T.rej[t][2] = s1.x; T.rej[t][3] = s1.y;
        key = nk;
    }
    key = kd;
    for (int t = 0; t < CHAIN; ++t) {
        CU2 nk  = ctf(key.x, key.y, 0u, 0u);
        CU2 sub = ctf(key.x, key.y, 0u, 1u);
        T.kn[t][0] = sub.x; T.kn[t][1] = sub.y;
        key = nk;
    }
    key = kp;
    for (int t = 0; t < CHAIN; ++t) {
        CU2 nk  = ctf(key.x, key.y, 0u, 0u);
        CU2 sub = ctf(key.x, key.y, 0u, 1u);
        T.knp[t][0] = sub.x; T.knp[t][1] = sub.y;
        key = nk;
    }
    return T;
}

__constant__ Tabs c_tabs = make_tabs();

// ---------------- Threefry-2x32 device --------------------------------------
__device__ __forceinline__ uint2 tf2x32(uint32_t k0, uint32_t k1,
                                        uint32_t x0, uint32_t x1)
{
    uint32_t k2 = k0 ^ k1 ^ 0x1BD11BDAu;
    x0 += k0; x1 += k1;
#define TF_RND(r) { x0 += x1; x1 = __funnelshift_l(x1, x1, (r)); x1 ^= x0; }
    TF_RND(13) TF_RND(15) TF_RND(26) TF_RND(6)
    x0 += k1; x1 += k2 + 1u;
    TF_RND(17) TF_RND(29) TF_RND(16) TF_RND(24)
    x0 += k2; x1 += k0 + 2u;
    TF_RND(13) TF_RND(15) TF_RND(26) TF_RND(6)
    x0 += k0; x1 += k1 + 3u;
    TF_RND(17) TF_RND(29) TF_RND(16) TF_RND(24)
    x0 += k1; x1 += k2 + 4u;
    TF_RND(13) TF_RND(15) TF_RND(26) TF_RND(6)
    x0 += k2; x1 += k0 + 5u;
#undef TF_RND
    return make_uint2(x0, x1);
}

__device__ __forceinline__ uint32_t rbits(uint2 k, uint32_t i)
{
    uint2 r = tf2x32(k.x, k.y, 0u, i);
    return r.x ^ r.y;
}

__device__ __forceinline__ float u01(uint32_t bits)
{
    return __uint_as_float((bits >> 9) | 0x3f800000u) - 1.0f;
}

// ---------------- XLA-style lgamma (Lanczos g=7, f32) ------------------------
__device__ __forceinline__ float lgamma_xla(float x)
{
    float z = __fsub_rn(x, 1.0f);
    float sum = 0.99999999999980993f;
    sum = __fadd_rn(sum, __fdiv_rn(676.5203681218851f,      __fadd_rn(z, 1.0f)));
    sum = __fadd_rn(sum, __fdiv_rn(-1259.1392167224028f,    __fadd_rn(z, 2.0f)));
    sum = __fadd_rn(sum, __fdiv_rn(771.32342877765313f,     __fadd_rn(z, 3.0f)));
    sum = __fadd_rn(sum, __fdiv_rn(-176.61502916214059f,    __fadd_rn(z, 4.0f)));
    sum = __fadd_rn(sum, __fdiv_rn(12.507343278686905f,     __fadd_rn(z, 5.0f)));
    sum = __fadd_rn(sum, __fdiv_rn(-0.13857109526572012f,   __fadd_rn(z, 6.0f)));
    sum = __fadd_rn(sum, __fdiv_rn(9.9843695780195716e-6f,  __fadd_rn(z, 7.0f)));
    sum = __fadd_rn(sum, __fdiv_rn(1.5056327351493116e-7f,  __fadd_rn(z, 8.0f)));
    float t     = __fadd_rn(7.5f, z);
    float log_t = __fadd_rn(2.0149030205422647f, log1pf(__fdiv_rn(z, 7.5f)));
    float r = __fadd_rn(0.91893853320467274f, __fmul_rn(__fadd_rn(z, 0.5f), log_t));
    r = __fsub_rn(r, t);
    r = __fadd_rn(r, logf(sum));
    return r;
}

// ---------------- XLA erf_inv (Giles polynomial, f32) ------------------------
__device__ __forceinline__ float erfinv_xla(float x)
{
    float w = -log1pf(-__fmul_rn(x, x));
    float p;
    if (w < 5.0f) {
        w = __fsub_rn(w, 2.5f);
        p = 2.81022636e-08f;
        p = fmaf(p, w, 3.43273939e-07f);
        p = fmaf(p, w, -3.5233877e-06f);
        p = fmaf(p, w, -4.39150654e-06f);
        p = fmaf(p, w, 0.00021858087f);
        p = fmaf(p, w, -0.00125372503f);
        p = fmaf(p, w, -0.00417768164f);
        p = fmaf(p, w, 0.246640727f);
        p = fmaf(p, w, 1.50140941f);
    } else {
        w = __fsub_rn(sqrtf(w), 3.0f);
        p = -0.000200214257f;
        p = fmaf(p, w, 0.000100950558f);
        p = fmaf(p, w, 0.00134934322f);
        p = fmaf(p, w, -0.00367342844f);
        p = fmaf(p, w, 0.00573950773f);
        p = fmaf(p, w, -0.0076224613f);
        p = fmaf(p, w, 0.00943887047f);
        p = fmaf(p, w, 1.00167406f);
        p = fmaf(p, w, 2.83297682f);
    }
    return __fmul_rn(p, x);
}

// ---------------- Poisson: Knuth (lam < 10) ----------------------------------
__device__ __forceinline__ float poisson_knuth(float lam, uint32_t i,
                                               const uint32_t (*ch)[2])
{
    float neg = -lam;
    float lp = 0.0f;
    float k  = 0.0f;
#pragma unroll 1
    for (int t = 0; t < CHAIN; ++t) {
        if (!(lp > neg)) break;
        k  = __fadd_rn(k, 1.0f);
        lp = __fadd_rn(lp, logf(u01(rbits(make_uint2(ch[t][0], ch[t][1]), i))));
    }
    return __fsub_rn(k, 1.0f);
}

// ---------------- Hormann rejection ------------------------------------------
struct RejP { float lam, log_lam, b, a, inv_alpha, v_r, two_a; };

__device__ __forceinline__ RejP make_rejp(float lam)
{
    RejP P;
    P.lam       = lam;
    P.log_lam   = logf(lam);
    P.b         = __fadd_rn(0.931f, __fmul_rn(2.53f, sqrtf(lam)));
    P.a         = __fadd_rn(-0.059f, __fmul_rn(0.02483f, P.b));
    P.inv_alpha = __fadd_rn(1.1239f, __fdiv_rn(1.1328f, __fsub_rn(P.b, 3.4f)));
    P.v_r       = __fsub_rn(0.9277f, __fdiv_rn(3.6224f, __fsub_rn(P.b, 2.0f)));
    P.two_a     = __fmul_rn(2.0f, P.a);
    return P;
}

// one rejection iteration; accept boolean bitwise-identical vs jax.
// lgamma(k+1) comes from the smem table (built with the identical routine).
__device__ __forceinline__ bool rej_step(const RejP& P, uint32_t i, uint4 c,
                                         const float* lgtab, float* kout)
{
    float u  = __fsub_rn(u01(rbits(make_uint2(c.x, c.y), i)), 0.5f);
    float v  = u01(rbits(make_uint2(c.z, c.w), i));
    float us = __fsub_rn(0.5f, fabsf(u));
    float k  = floorf(__fadd_rn(__fadd_rn(
                 __fmul_rn(__fadd_rn(__fdiv_rn(P.two_a, us), P.b), u), P.lam), 0.43f));
    *kout = k;

    if ((us >= 0.07f) && (v <= P.v_r)) return true;                 // accept1
    if ((k < 0.0f) || ((us < 0.013f) && (v > us))) return false;    // reject

    float s = logf(__fdiv_rn(__fmul_rn(v, P.inv_alpha),
                   __fadd_rn(__fdiv_rn(P.a, __fmul_rn(us, us)), P.b)));
    const int j = (int)k + 1;                                        // k >= 0 here
    const float lg = (j < LGTAB) ? lgtab[j] : lgamma_xla(__fadd_rn(k, 1.0f));
    float t = __fsub_rn(__fadd_rn(-P.lam, __fmul_rn(k, P.log_lam)), lg);
    return (s <= t);                                                 // accept2
}

__device__ __forceinline__ uint4 rej_key(int t)
{
    return *reinterpret_cast<const uint4*>(c_tabs.rej[t]);
}

// ================================================================================
// Fused persistent kernel (R12 base, 121.3us): 1024 blocks x 256 threads,
// pair-split planes. R15 delta: 512-entry smem lgamma table (values computed by
// the identical lgamma_xla routine => outputs bit-identical) replaces the ~180-instr
// lgamma call on the warp-ubiquitous accept2 slow path of both scans.
// __launch_bounds__(256, 7): 148*7=1036 >= 1024 blocks co-resident => barrier safe.
// ================================================================================
__global__ void __launch_bounds__(NTHR, 7)
capF(const float* __restrict__ spec, const float* __restrict__ filt,
     float* __restrict__ out)
{
    __shared__ float4 sh[2][PAIRS];    // per-half partial sums (4KB)
    __shared__ float  s_lg[LGTAB];     // lgamma(j) table (2KB)
    __shared__ int s_fmax;
    __shared__ int s_F;

    const int tid = threadIdx.x;
    if (tid == 0) s_fmax = 0;

    // lgamma table: identical routine => bit-identical values (2 calls/thread)
    for (int j = tid; j < LGTAB; j += NTHR)
        s_lg[j] = lgamma_xla((float)j);

    const int s  = tid >> 7;                       // 0: planes 0..55, 1: 56..111
    const int pl = tid & 127;                      // pair-local group index
    const int pair_gid = blockIdx.x * PAIRS + pl;  // 0..131071
    const int e0  = pair_gid << 2;                 // first of 4 elements
    const int b   = e0 >> 16;
    const int hw4 = (e0 & 65535) >> 2;
    const int p0  = s * HALF_P;

    const float4* sp = reinterpret_cast<const float4*>(spec)
                       + (long)b * ROWS_F4 + (long)p0 * PLANE_F4 + hw4;
    const float4* fp = reinterpret_cast<const float4*>(filt)
                       + (long)b * ROWS_F4 + (long)p0 * PLANE_F4 + hw4;

    // constant output planes early (each thread: its float2 slice x2)
    float2* o2 = reinterpret_cast<float2*>(out);
    const int q2 = (e0 >> 1) + s;
    o2[2 * N_H + q2] = make_float2(0.5f, 0.5f);
    o2[3 * N_H + q2] = make_float2(0.25f, 0.25f);

    // ---- streaming quarter 1: my planes [0..28) (sequential within half) ----
    float4 acc = make_float4(0.f, 0.f, 0.f, 0.f);
#pragma unroll 4
    for (int p = 0; p < QTR_P; ++p) {
        float4 a = __ldcs(sp + (long)p * PLANE_F4);
        float4 f = __ldcs(fp + (long)p * PLANE_F4);
        acc.x = __fadd_rn(acc.x, __fmul_rn(a.x, f.x));
        acc.y = __fadd_rn(acc.y, __fmul_rn(a.y, f.y));
        acc.z = __fadd_rn(acc.z, __fmul_rn(a.z, f.z));
        acc.w = __fadd_rn(acc.w, __fmul_rn(a.w, f.w));
    }

    // ---- index-only RNG (dn, gn) for MY 2 elements: fills load-stall cycles ----
    const uint2 kg = make_uint2(c_tabs.kg[0], c_tabs.kg[1]);
    float raw2[2];
#pragma unroll 1
    for (int v = 0; v < 2; ++v) {
        const uint32_t i = (uint32_t)(e0 + 2 * s + v);
        float dn = poisson_knuth(0.5f, i, c_tabs.kn);

        float f  = u01(rbits(kg, i));
        float uu = __fadd_rn(__fmul_rn(f, 1.99999994f), -0.99999994f);
        uu = fmaxf(uu, -0.99999994f);
        float gn = __fmul_rn(__fmul_rn(1.4142135623730951f, erfinv_xla(uu)), 0.5f);

        raw2[v] = __fadd_rn(dn, gn);
    }

    // ---- streaming quarter 2: my planes [28..56) ----
#pragma unroll 4
    for (int p = QTR_P; p < HALF_P; ++p) {
        float4 a = __ldcs(sp + (long)p * PLANE_F4);
        float4 f = __ldcs(fp + (long)p * PLANE_F4);
        acc.x = __fadd_rn(acc.x, __fmul_rn(a.x, f.x));
        acc.y = __fadd_rn(acc.y, __fmul_rn(a.y, f.y));
        acc.z = __fadd_rn(acc.z, __fmul_rn(a.z, f.z));
        acc.w = __fadd_rn(acc.w, __fmul_rn(a.w, f.w));
    }

    // ---- combine halves: lam = (h0 + h1) + CONS ----
    sh[s][pl] = acc;
    __syncthreads();
    const float4 h0 = sh[0][pl];
    const float4 h1 = sh[1][pl];

    float lam2[2];
    {
        const float h0v[4] = {h0.x, h0.y, h0.z, h0.w};
        const float h1v[4] = {h1.x, h1.y, h1.z, h1.w};
        lam2[0] = __fadd_rn(__fadd_rn(h0v[2 * s],     h1v[2 * s]),     1e-10f);
        lam2[1] = __fadd_rn(__fadd_rn(h0v[2 * s + 1], h1v[2 * s + 1]), 1e-10f);
    }

    // peak output (my float2 slice)
    o2[N_H + q2] = make_float2(lam2[0], lam2[1]);

    // ---- forward first-accept scan for my 2 elements ----
    int fmax = 0;
#pragma unroll 1
    for (int v = 0; v < 2; ++v) {
        const uint32_t i = (uint32_t)(e0 + 2 * s + v);
        const float lam_rej = (lam2[v] < 10.0f) ? 1e5f : lam2[v];
        RejP P = make_rejp(lam_rej);
        float kdum;
        int fe = CHAIN - 1;
#pragma unroll 1
        for (int t = 0; t < CHAIN; ++t) {
            if (rej_step(P, i, rej_key(t), s_lg, &kdum)) { fe = t; break; }
        }
        fmax = max(fmax, fe);
    }
    atomicMax(&s_fmax, fmax);

    __syncthreads();                       // s_fmax final

    // ---- software grid barrier (replay-safe) ----
    if (tid == 0) {
        atomicMax(&g_F, s_fmax);
        __threadfence();
        unsigned ticket = atomicAdd(&g_barrier, 1u);
        if (ticket == NBLK - 1u) {
            atomicExch(&g_barrier, 0u);
        } else {
            while (*((volatile unsigned*)&g_barrier) != 0u)
                __nanosleep(64);
        }
        __threadfence();
        s_F = *((volatile int*)&g_F);
    }
    __syncthreads();
    const int F = min(s_F, CHAIN - 1);

    // ---- final: LAST accept via backward scan from F, my 2 elements ----
    float noisy2[2];
#pragma unroll 1
    for (int v = 0; v < 2; ++v) {
        const uint32_t i = (uint32_t)(e0 + 2 * s + v);
        const float lam = lam2[v];
        float pn;
        if (lam < 10.0f) {
            pn = poisson_knuth(lam, i, c_tabs.knp);
        } else {
            RejP P = make_rejp(lam);
            float pnk = -1.0f, k;
#pragma unroll 1
            for (int t = F; t >= 0; --t) {
                if (rej_step(P, i, rej_key(t), s_lg, &k)) { pnk = k; break; }
            }
            pn = pnk;
        }
        noisy2[v] = __fdiv_rn(__fmul_rn(__fadd_rn(pn, raw2[v]), 10.0f), 255.0f);
    }

    o2[q2] = make_float2(noisy2[0], noisy2[1]);
}

extern "C" void kernel_launch(void* const* d_in, const int* in_sizes, int n_in,
                              void* d_out, int out_size)
{
    const float* spec = (const float*)d_in[0];
    const float* filt = (const float*)d_in[1];
    float* out = (float*)d_out;
    capF<<<NBLK, NTHR>>>(spec, filt, out);
}